// round 1
// baseline (speedup 1.0000x reference)
#include <cuda_runtime.h>
#include <cuda_bf16.h>

// ---------------------------------------------------------------------------
// CutsSelector: GNN edge-conv collapsed to scalar-per-node form.
//
//   msg[e]  = [x[dst], x[src], ea] @ g_w + g_b          (g_w: [257,128])
//   aggr[n] = segment_mean(msg, dst)                     (empty -> 0)
//   h[n]    = [x[n], aggr[n]] @ f_w + f_b                (f_w: [256,128])
//   probs   = sigmoid(h @ cls_w + cls_b);  y = probs > 0.5
//
// Since everything after x is linear until the sigmoid and only the scalar
// score per node is observed:
//   v  = f2 @ cls_w            u  = f1 @ cls_w
//   p  = Wd @ v                q  = Ws @ v
//   r  = we . v                s  = g_b . v
//   c0 = f_b . cls_w + cls_b
//   t[n] = x[n] . q
//   acc[n] = sum_{e: dst=n} ( t[src[e]] + r*ea[e] );   cnt[n] = #edges
//   score[n] = x[n].u + c0 + (cnt>0 ? x[n].p + acc[n]/cnt + s : 0)
//   probs = sigmoid(score)
// ---------------------------------------------------------------------------

#define C 128
#define NODE_CAP 24576

__device__ float g_vec_u[C];
__device__ float g_vec_p[C];
__device__ float g_vec_q[C];
__device__ float g_scalar_r;
__device__ float g_scalar_s;
__device__ float g_scalar_c0;
__device__ int   g_idx_is64;

__device__ float g_t[NODE_CAP];
__device__ float g_acc[NODE_CAP];
__device__ float g_cnt[NODE_CAP];

__device__ __forceinline__ float block_reduce128(float val, volatile float* sh, int k) {
    sh[k] = val;
    __syncthreads();
    for (int st = 64; st > 0; st >>= 1) {
        if (k < st) sh[k] += sh[k + st];
        __syncthreads();
    }
    float res = sh[0];
    __syncthreads();
    return res;
}

// One block, 128 threads: derive all small vectors/scalars; sniff index dtype.
__global__ void setup_kernel(const float* __restrict__ g_w,   // [257,128]
                             const float* __restrict__ g_b,   // [128]
                             const float* __restrict__ f_w,   // [256,128]
                             const float* __restrict__ f_b,   // [128]
                             const float* __restrict__ cls_w, // [128]
                             const float* __restrict__ cls_b) // [1]
{
    __shared__ float sv[C];
    __shared__ float sred[C];
    const int k = threadIdx.x;  // 0..127

    // u[k] = sum_o f_w[k][o]   * cls_w[o]   (f1 rows 0..127)
    // v[k] = sum_o f_w[128+k][o] * cls_w[o] (f2 rows 128..255)
    float uk = 0.f, vk = 0.f;
    #pragma unroll 8
    for (int j = 0; j < C; j++) {
        float c = __ldg(&cls_w[j]);
        uk += __ldg(&f_w[k * C + j]) * c;
        vk += __ldg(&f_w[(C + k) * C + j]) * c;
    }
    sv[k] = vk;
    __syncthreads();

    // p[k] = sum_o g_w[k][o] * v[o]   (Wd rows 0..127)
    // q[k] = sum_o g_w[128+k][o] * v[o]  (Ws rows 128..255)
    float pk = 0.f, qk = 0.f;
    #pragma unroll 8
    for (int j = 0; j < C; j++) {
        float vj = sv[j];
        pk += __ldg(&g_w[k * C + j]) * vj;
        qk += __ldg(&g_w[(C + k) * C + j]) * vj;
    }
    g_vec_u[k] = uk;
    g_vec_p[k] = pk;
    g_vec_q[k] = qk;

    // r = we . v ; s = g_b . v ; c0 = f_b . cls_w + cls_b
    float r = block_reduce128(__ldg(&g_w[2 * C * C + k]) * sv[k], sred, k);
    float s = block_reduce128(__ldg(&g_b[k]) * sv[k], sred, k);
    float c = block_reduce128(__ldg(&f_b[k]) * __ldg(&cls_w[k]), sred, k);
    if (k == 0) {
        g_scalar_r  = r;
        g_scalar_s  = s;
        g_scalar_c0 = c + __ldg(&cls_b[0]);
    }
}

// Index-dtype sniff: if edge_index is int64 (values < 2^31, nonneg), the
// int32 view shows zeros at every odd position.
__global__ void sniff_kernel(const void* __restrict__ edge_index) {
    const int* p = (const int*)edge_index;
    int lane = threadIdx.x;  // 0..31
    int ok = (p[2 * lane + 1] == 0) &&
             (p[2 * (lane + 32) + 1] == 0) &&
             (p[2 * (lane + 64) + 1] == 0);
    unsigned b = __ballot_sync(0xffffffffu, ok);
    if (lane == 0) g_idx_is64 = (b == 0xffffffffu) ? 1 : 0;
}

// One warp per node: t[n] = x[n].q ; zero accumulators.
__global__ void t_kernel(const float* __restrict__ x, int N) {
    __shared__ float sq[C];
    if (threadIdx.x < C) sq[threadIdx.x] = g_vec_q[threadIdx.x];
    __syncthreads();

    int warp = (int)((blockIdx.x * (unsigned)blockDim.x + threadIdx.x) >> 5);
    int lane = threadIdx.x & 31;
    if (warp >= N) return;

    const float4* xr = (const float4*)(x + (size_t)warp * C);
    float4 xv = xr[lane];
    const float4* q4 = (const float4*)sq;
    float4 qv = q4[lane];
    float part = xv.x * qv.x + xv.y * qv.y + xv.z * qv.z + xv.w * qv.w;
    #pragma unroll
    for (int o = 16; o > 0; o >>= 1) part += __shfl_xor_sync(0xffffffffu, part, o);

    if (lane == 0) {
        g_t[warp]   = part;
        g_acc[warp] = 0.f;
        g_cnt[warp] = 0.f;
    }
}

// Per edge: acc[dst] += t[src] + r*ea ;  cnt[dst] += 1.
__global__ void edge_kernel(const void* __restrict__ edge_index,
                            const float* __restrict__ edge_attr,
                            long long E) {
    long long e = (long long)blockIdx.x * blockDim.x + threadIdx.x;
    if (e >= E) return;

    long long src, dst;
    if (g_idx_is64) {
        const long long* p = (const long long*)edge_index;
        src = p[e];
        dst = p[E + e];
    } else {
        const int* p = (const int*)edge_index;
        src = p[e];
        dst = p[E + e];
    }
    float val = __ldg(&g_t[src]) + edge_attr[e] * g_scalar_r;
    atomicAdd(&g_acc[dst], val);
    atomicAdd(&g_cnt[dst], 1.0f);
}

// One warp per node: score -> probs -> (y, probs) output.
__global__ void node_out_kernel(const float* __restrict__ x,
                                float* __restrict__ out,
                                int N, int twopart) {
    __shared__ float su[C];
    __shared__ float sp[C];
    if (threadIdx.x < C) {
        su[threadIdx.x] = g_vec_u[threadIdx.x];
        sp[threadIdx.x] = g_vec_p[threadIdx.x];
    }
    __syncthreads();

    int warp = (int)((blockIdx.x * (unsigned)blockDim.x + threadIdx.x) >> 5);
    int lane = threadIdx.x & 31;
    if (warp >= N) return;

    const float4* xr = (const float4*)(x + (size_t)warp * C);
    float4 xv = xr[lane];
    const float4* u4 = (const float4*)su;
    const float4* p4 = (const float4*)sp;
    float4 uv = u4[lane];
    float4 pv = p4[lane];
    float du = xv.x * uv.x + xv.y * uv.y + xv.z * uv.z + xv.w * uv.w;
    float dp = xv.x * pv.x + xv.y * pv.y + xv.z * pv.z + xv.w * pv.w;
    #pragma unroll
    for (int o = 16; o > 0; o >>= 1) {
        du += __shfl_xor_sync(0xffffffffu, du, o);
        dp += __shfl_xor_sync(0xffffffffu, dp, o);
    }

    if (lane == 0) {
        float cnt = g_cnt[warp];
        float score = du + g_scalar_c0;
        if (cnt > 0.f) score += dp + g_acc[warp] / cnt + g_scalar_s;
        float probs = 1.0f / (1.0f + expf(-score));
        if (twopart) {
            out[warp]     = (probs > 0.5f) ? 1.0f : 0.0f;
            out[N + warp] = probs;
        } else {
            out[warp] = probs;
        }
    }
}

extern "C" void kernel_launch(void* const* d_in, const int* in_sizes, int n_in,
                              void* d_out, int out_size) {
    // metadata order: x_a, edge_index, edge_attr, g_w, g_b, f_w, f_b, cls_w, cls_b
    const float* x_a       = (const float*)d_in[0];
    const void*  edge_index=               d_in[1];
    const float* edge_attr = (const float*)d_in[2];
    const float* g_w       = (const float*)d_in[3];
    const float* g_b       = (const float*)d_in[4];
    const float* f_w       = (const float*)d_in[5];
    const float* f_b       = (const float*)d_in[6];
    const float* cls_w     = (const float*)d_in[7];
    const float* cls_b     = (const float*)d_in[8];
    float* out = (float*)d_out;

    const int       N = in_sizes[0] / C;       // 20000
    const long long E = (long long)in_sizes[2];// 640000 (edge_attr count, dim=1)
    const int twopart = (out_size >= 2 * N) ? 1 : 0;

    setup_kernel<<<1, C>>>(g_w, g_b, f_w, f_b, cls_w, cls_b);
    sniff_kernel<<<1, 32>>>(edge_index);

    const int nodes_per_blk = 256 / 32;  // 8 warps/block
    const int nblk_nodes = (N + nodes_per_blk - 1) / nodes_per_blk;
    t_kernel<<<nblk_nodes, 256>>>(x_a, N);

    const int nblk_edges = (int)((E + 255) / 256);
    edge_kernel<<<nblk_edges, 256>>>(edge_index, edge_attr, E);

    node_out_kernel<<<nblk_nodes, 256>>>(x_a, out, N, twopart);
}

// round 2
// speedup vs baseline: 2.4758x; 2.4758x over previous
#include <cuda_runtime.h>
#include <cuda_bf16.h>

// ---------------------------------------------------------------------------
// CutsSelector collapsed to scalar-per-node form (see R1 derivation):
//   v  = f2 @ cls_w ; u = f1 @ cls_w ; p = Wd @ v ; q = Ws @ v
//   r  = we.v ; s = g_b.v ; c0 = f_b.cls_w + cls_b
//   t[n]  = x[n].q ;  du[n] = x[n].u ;  dp[n] = x[n].p
//   acc[n], cnt[n] = segment_sum over dst of (t[src] + r*ea), 1
//   score = du + c0 + (cnt>0 ? dp + acc/cnt + s : 0) ; probs = sigmoid(score)
// ---------------------------------------------------------------------------

#define C 128
#define NODE_CAP 24576

__device__ float g_vec_u[C];
__device__ float g_vec_p[C];
__device__ float g_vec_q[C];
__device__ float g_scalar_r;
__device__ float g_scalar_s;
__device__ float g_scalar_c0;
__device__ int   g_idx_is64;

__device__ float  g_t[NODE_CAP];
__device__ float  g_du[NODE_CAP];
__device__ float  g_dp[NODE_CAP];
__device__ float2 g_accnt[NODE_CAP];   // {acc, cnt} interleaved for v2 red

__device__ __forceinline__ float warp_sum(float v) {
    #pragma unroll
    for (int o = 16; o > 0; o >>= 1) v += __shfl_xor_sync(0xffffffffu, v, o);
    return v;
}

// One block, 1024 threads (32 warps). Warp-per-dot-product matvecs + sniff.
__global__ void setup_kernel(const float* __restrict__ g_w,   // [257,128]
                             const float* __restrict__ g_b,   // [128]
                             const float* __restrict__ f_w,   // [256,128]
                             const float* __restrict__ f_b,   // [128]
                             const float* __restrict__ cls_w, // [128]
                             const float* __restrict__ cls_b, // [1]
                             const void* __restrict__ edge_index)
{
    __shared__ float scls[C];
    __shared__ float sv[C];
    const int tid  = threadIdx.x;
    const int wi   = tid >> 5;
    const int lane = tid & 31;

    // Index-dtype sniff (warp 0): int64 indices (nonneg < 2^31) show zeros at
    // every odd int32 position.
    if (wi == 0) {
        const int* p = (const int*)edge_index;
        int ok = (p[2 * lane + 1] == 0) &&
                 (p[2 * (lane + 32) + 1] == 0) &&
                 (p[2 * (lane + 64) + 1] == 0);
        unsigned b = __ballot_sync(0xffffffffu, ok);
        if (lane == 0) g_idx_is64 = (b == 0xffffffffu) ? 1 : 0;
    }

    if (tid < C) scls[tid] = __ldg(&cls_w[tid]);
    __syncthreads();

    const float4* c4 = (const float4*)scls;
    float4 cc = c4[lane];

    // Stage 1: 256 dots of f_w rows with cls_w. Warp wi handles rows wi*8..+7.
    // rows 0..127 -> u ; rows 128..255 -> v.
    #pragma unroll
    for (int j = 0; j < 8; j++) {
        int d = wi * 8 + j;                       // 0..255
        const float4* rw = (const float4*)(f_w + (size_t)d * C);
        float4 a = rw[lane];
        float part = warp_sum(a.x * cc.x + a.y * cc.y + a.z * cc.z + a.w * cc.w);
        if (lane == 0) {
            if (d < C) g_vec_u[d] = part;
            else       sv[d - C]  = part;
        }
    }
    __syncthreads();

    const float4* v4 = (const float4*)sv;
    float4 vv = v4[lane];

    // Stage 2: 256 dots of g_w rows with v. rows 0..127 -> p ; 128..255 -> q.
    #pragma unroll
    for (int j = 0; j < 8; j++) {
        int d = wi * 8 + j;
        const float4* rw = (const float4*)(g_w + (size_t)d * C);
        float4 a = rw[lane];
        float part = warp_sum(a.x * vv.x + a.y * vv.y + a.z * vv.z + a.w * vv.w);
        if (lane == 0) {
            if (d < C) g_vec_p[d]     = part;
            else       g_vec_q[d - C] = part;
        }
    }

    // Stage 3 (warp 0): r = we.v ; s = g_b.v ; c0 = f_b.cls_w + cls_b
    if (wi == 0) {
        float r = 0.f, s = 0.f, c = 0.f;
        #pragma unroll
        for (int k = lane; k < C; k += 32) {
            float vk = sv[k];
            r += __ldg(&g_w[2 * C * C + k]) * vk;
            s += __ldg(&g_b[k]) * vk;
            c += __ldg(&f_b[k]) * scls[k];
        }
        r = warp_sum(r); s = warp_sum(s); c = warp_sum(c);
        if (lane == 0) {
            g_scalar_r  = r;
            g_scalar_s  = s;
            g_scalar_c0 = c + __ldg(&cls_b[0]);
        }
    }
}

// One warp per node: t = x.q, du = x.u, dp = x.p ; zero accumulators.
__global__ void t_kernel(const float* __restrict__ x, int N) {
    __shared__ float sq[C];
    __shared__ float su[C];
    __shared__ float sp[C];
    if (threadIdx.x < C) {
        sq[threadIdx.x] = g_vec_q[threadIdx.x];
        su[threadIdx.x] = g_vec_u[threadIdx.x];
        sp[threadIdx.x] = g_vec_p[threadIdx.x];
    }
    __syncthreads();

    int node = (int)((blockIdx.x * (unsigned)blockDim.x + threadIdx.x) >> 5);
    int lane = threadIdx.x & 31;
    if (node >= N) return;

    const float4* xr = (const float4*)(x + (size_t)node * C);
    float4 xv = xr[lane];
    float4 qv = ((const float4*)sq)[lane];
    float4 uv = ((const float4*)su)[lane];
    float4 pv = ((const float4*)sp)[lane];

    float dq = xv.x * qv.x + xv.y * qv.y + xv.z * qv.z + xv.w * qv.w;
    float du = xv.x * uv.x + xv.y * uv.y + xv.z * uv.z + xv.w * uv.w;
    float dp = xv.x * pv.x + xv.y * pv.y + xv.z * pv.z + xv.w * pv.w;
    #pragma unroll
    for (int o = 16; o > 0; o >>= 1) {
        dq += __shfl_xor_sync(0xffffffffu, dq, o);
        du += __shfl_xor_sync(0xffffffffu, du, o);
        dp += __shfl_xor_sync(0xffffffffu, dp, o);
    }

    if (lane == 0) {
        g_t[node]     = dq;
        g_du[node]    = du;
        g_dp[node]    = dp;
        g_accnt[node] = make_float2(0.f, 0.f);
    }
}

// Per edge: {acc,cnt}[dst] += {t[src] + r*ea, 1}  via one v2 reduction.
__global__ void edge_kernel(const void* __restrict__ edge_index,
                            const float* __restrict__ edge_attr,
                            long long E) {
    long long e = (long long)blockIdx.x * blockDim.x + threadIdx.x;
    if (e >= E) return;

    long long src, dst;
    if (g_idx_is64) {
        const long long* p = (const long long*)edge_index;
        src = p[e];
        dst = p[E + e];
    } else {
        const int* p = (const int*)edge_index;
        src = p[e];
        dst = p[E + e];
    }
    float val = __ldg(&g_t[src]) + edge_attr[e] * g_scalar_r;
    float2* a = &g_accnt[dst];
    asm volatile("red.global.add.v2.f32 [%0], {%1, %2};"
                 :: "l"(a), "f"(val), "f"(1.0f)
                 : "memory");
}

// One thread per node: score -> probs -> (y, probs).
__global__ void out_kernel(float* __restrict__ out, int N, int twopart) {
    int n = blockIdx.x * blockDim.x + threadIdx.x;
    if (n >= N) return;
    float2 ac = g_accnt[n];
    float score = g_du[n] + g_scalar_c0;
    if (ac.y > 0.f) score += g_dp[n] + ac.x / ac.y + g_scalar_s;
    float probs = 1.0f / (1.0f + expf(-score));
    if (twopart) {
        out[n]     = (probs > 0.5f) ? 1.0f : 0.0f;
        out[N + n] = probs;
    } else {
        out[n] = probs;
    }
}

extern "C" void kernel_launch(void* const* d_in, const int* in_sizes, int n_in,
                              void* d_out, int out_size) {
    // metadata order: x_a, edge_index, edge_attr, g_w, g_b, f_w, f_b, cls_w, cls_b
    const float* x_a        = (const float*)d_in[0];
    const void*  edge_index =               d_in[1];
    const float* edge_attr  = (const float*)d_in[2];
    const float* g_w        = (const float*)d_in[3];
    const float* g_b        = (const float*)d_in[4];
    const float* f_w        = (const float*)d_in[5];
    const float* f_b        = (const float*)d_in[6];
    const float* cls_w      = (const float*)d_in[7];
    const float* cls_b      = (const float*)d_in[8];
    float* out = (float*)d_out;

    const int       N = in_sizes[0] / C;        // 20000
    const long long E = (long long)in_sizes[2]; // 640000
    const int twopart = (out_size >= 2 * N) ? 1 : 0;

    setup_kernel<<<1, 1024>>>(g_w, g_b, f_w, f_b, cls_w, cls_b, edge_index);

    const int warps_per_blk = 256 / 32;
    const int nblk_nodes = (N + warps_per_blk - 1) / warps_per_blk;
    t_kernel<<<nblk_nodes, 256>>>(x_a, N);

    const int nblk_edges = (int)((E + 255) / 256);
    edge_kernel<<<nblk_edges, 256>>>(edge_index, edge_attr, E);

    out_kernel<<<(N + 255) / 256, 256>>>(out, N, twopart);
}